// round 5
// baseline (speedup 1.0000x reference)
#include <cuda_runtime.h>
#include <math.h>

#define B_   4
#define S_   2048
#define D_   1024
#define H_   16
#define DK_  64

// ---------------- scratch (static device globals: allocation-free) ----------------
__device__ float g_Qp[(size_t)B_ * H_ * S_ * DK_];   // [B,H,S,dk]
__device__ float g_Kp[(size_t)B_ * H_ * S_ * DK_];
__device__ float g_Vp[(size_t)B_ * H_ * S_ * DK_];
__device__ float g_At[(size_t)B_ * S_ * D_];         // attention out, merged heads [B,S,D]

// =====================================================================
// GEMM:  C = A[8192 x 1024] @ W^T[1024 x 1024] + bias
// A row-major [M,K], W row-major [N,K]  (both K-contiguous -> NT gemm)
// SPLIT=true  : write C in head-split layout [B,H,S,dk]
// SPLIT=false : write C row-major [M,N]
// BM=BN=128, BK=8, 256 threads, 8x8 per-thread fragment
// =====================================================================
template <bool SPLIT>
__global__ __launch_bounds__(256, 2)
void gemm_nt(const float* __restrict__ A, const float* __restrict__ W,
             const float* __restrict__ bias, float* __restrict__ C)
{
    __shared__ float As[8 * 132];   // k-major: As[k*132 + row]
    __shared__ float Bs[8 * 132];

    const int tid = threadIdx.x;
    const int tx  = tid & 15;       // 0..15 -> N frag
    const int ty  = tid >> 4;       // 0..15 -> M frag
    const int bm  = blockIdx.y;     // 0..63
    const int bn  = blockIdx.x;     // 0..7

    const int srow = tid >> 1;          // 0..127
    const int scol = (tid & 1) * 4;     // 0 or 4

    const float* Ag = A + ((size_t)bm * 128 + srow) * 1024 + scol;
    const float* Wg = W + ((size_t)bn * 128 + srow) * 1024 + scol;

    float acc[8][8];
#pragma unroll
    for (int i = 0; i < 8; i++)
#pragma unroll
        for (int j = 0; j < 8; j++) acc[i][j] = 0.0f;

    for (int kt = 0; kt < 128; kt++) {
        const float4 av = *(const float4*)(Ag + kt * 8);
        const float4 wv = *(const float4*)(Wg + kt * 8);
        __syncthreads();   // previous tile fully consumed
        As[(scol + 0) * 132 + srow] = av.x;
        As[(scol + 1) * 132 + srow] = av.y;
        As[(scol + 2) * 132 + srow] = av.z;
        As[(scol + 3) * 132 + srow] = av.w;
        Bs[(scol + 0) * 132 + srow] = wv.x;
        Bs[(scol + 1) * 132 + srow] = wv.y;
        Bs[(scol + 2) * 132 + srow] = wv.z;
        Bs[(scol + 3) * 132 + srow] = wv.w;
        __syncthreads();

#pragma unroll
        for (int k = 0; k < 8; k++) {
            const float4 a0 = *(const float4*)&As[k * 132 + ty * 4];
            const float4 a1 = *(const float4*)&As[k * 132 + 64 + ty * 4];
            const float4 b0 = *(const float4*)&Bs[k * 132 + tx * 4];
            const float4 b1 = *(const float4*)&Bs[k * 132 + 64 + tx * 4];
            const float av8[8] = {a0.x, a0.y, a0.z, a0.w, a1.x, a1.y, a1.z, a1.w};
            const float bv8[8] = {b0.x, b0.y, b0.z, b0.w, b1.x, b1.y, b1.z, b1.w};
#pragma unroll
            for (int i = 0; i < 8; i++)
#pragma unroll
                for (int j = 0; j < 8; j++)
                    acc[i][j] = fmaf(av8[i], bv8[j], acc[i][j]);
        }
    }

    // epilogue
    float bl[8];
    const int n0 = bn * 128 + tx * 4;       // cols for j=0..3
    const int n1 = n0 + 64;                 // cols for j=4..7
#pragma unroll
    for (int j = 0; j < 4; j++) {
        bl[j]     = bias[n0 + j];
        bl[j + 4] = bias[n1 + j];
    }

#pragma unroll
    for (int i = 0; i < 8; i++) {
        const int r = bm * 128 + ((i < 4) ? (ty * 4 + i) : (64 + ty * 4 + (i - 4)));
        float4 lo = make_float4(acc[i][0] + bl[0], acc[i][1] + bl[1],
                                acc[i][2] + bl[2], acc[i][3] + bl[3]);
        float4 hi = make_float4(acc[i][4] + bl[4], acc[i][5] + bl[5],
                                acc[i][6] + bl[6], acc[i][7] + bl[7]);
        if (SPLIT) {
            const int b = r >> 11;          // r / 2048
            const int s = r & 2047;
            const int h0 = n0 >> 6, d0 = n0 & 63;
            const int h1 = n1 >> 6, d1 = n1 & 63;
            *(float4*)&C[(((size_t)b * H_ + h0) * S_ + s) * DK_ + d0] = lo;
            *(float4*)&C[(((size_t)b * H_ + h1) * S_ + s) * DK_ + d1] = hi;
        } else {
            *(float4*)&C[(size_t)r * 1024 + n0] = lo;
            *(float4*)&C[(size_t)r * 1024 + n1] = hi;
        }
    }
}

// =====================================================================
// Flash attention (fp32). One block = one (b,h) head x 64-query tile.
// 256 threads = 16x16 grid; 4x4 fragments with strided row ownership.
// SMEM: Qs[64][68], Ks[64][68] (reused as P^T), Vs[64][68] = 52224 B.
// Online softmax over 32 K/V tiles of 64. Output merged [B,S,D].
// =====================================================================
#define AST 68

__global__ __launch_bounds__(256)
void attn_kernel(const float* __restrict__ Q, const float* __restrict__ K,
                 const float* __restrict__ V, const int* __restrict__ mask,
                 float* __restrict__ O)
{
    extern __shared__ float sm[];
    float* Qs = sm;                 // 64 * AST
    float* Ks = sm + 64 * AST;      // 64 * AST  (reused for P^T)
    float* Vs = sm + 128 * AST;     // 64 * AST

    const int tid = threadIdx.x;
    const int tx  = tid & 15;
    const int ty  = tid >> 4;
    const int qb  = blockIdx.x;     // 0..31
    const int bh  = blockIdx.y;     // 0..63
    const int b   = bh >> 4;
    const int h   = bh & 15;

    const float* Qg = Q + ((size_t)bh * S_ + qb * 64) * DK_;
    const float* Kg = K + (size_t)bh * S_ * DK_;
    const float* Vg = V + (size_t)bh * S_ * DK_;
    const int*   Mg = mask + (size_t)(qb * 64) * S_;

    // load Q tile (64 x 64), coalesced float4
    for (int i = tid; i < 64 * 16; i += 256) {
        const int r = i >> 4;
        const int c = (i & 15) * 4;
        const float4 v = *(const float4*)(Qg + r * 64 + c);
        Qs[r * AST + c + 0] = v.x;
        Qs[r * AST + c + 1] = v.y;
        Qs[r * AST + c + 2] = v.z;
        Qs[r * AST + c + 3] = v.w;
    }

    float m_i[4], l_i[4], o[4][4];
#pragma unroll
    for (int i = 0; i < 4; i++) {
        m_i[i] = -1e30f;
        l_i[i] = 0.0f;
#pragma unroll
        for (int j = 0; j < 4; j++) o[i][j] = 0.0f;
    }

    for (int kt = 0; kt < S_ / 64; kt++) {
        __syncthreads();   // prior-tile consumers done (covers Qs visibility on iter 0)
        // load K,V tiles (64 x 64 each)
        for (int i = tid; i < 64 * 16; i += 256) {
            const int r = i >> 4;
            const int c = (i & 15) * 4;
            const float4 kv = *(const float4*)(Kg + (size_t)(kt * 64 + r) * 64 + c);
            Ks[r * AST + c + 0] = kv.x;
            Ks[r * AST + c + 1] = kv.y;
            Ks[r * AST + c + 2] = kv.z;
            Ks[r * AST + c + 3] = kv.w;
            const float4 vv = *(const float4*)(Vg + (size_t)(kt * 64 + r) * 64 + c);
            Vs[r * AST + c + 0] = vv.x;
            Vs[r * AST + c + 1] = vv.y;
            Vs[r * AST + c + 2] = vv.z;
            Vs[r * AST + c + 3] = vv.w;
        }
        __syncthreads();

        // S = Q @ K^T  : rows ty+16i, cols tx+16j
        float sc[4][4];
#pragma unroll
        for (int i = 0; i < 4; i++)
#pragma unroll
            for (int j = 0; j < 4; j++) sc[i][j] = 0.0f;

#pragma unroll 4
        for (int d = 0; d < 64; d += 4) {
            float4 aq[4], bk[4];
#pragma unroll
            for (int i = 0; i < 4; i++) aq[i] = *(const float4*)&Qs[(ty + 16 * i) * AST + d];
#pragma unroll
            for (int j = 0; j < 4; j++) bk[j] = *(const float4*)&Ks[(tx + 16 * j) * AST + d];
#pragma unroll
            for (int i = 0; i < 4; i++)
#pragma unroll
                for (int j = 0; j < 4; j++) {
                    sc[i][j] = fmaf(aq[i].x, bk[j].x, sc[i][j]);
                    sc[i][j] = fmaf(aq[i].y, bk[j].y, sc[i][j]);
                    sc[i][j] = fmaf(aq[i].z, bk[j].z, sc[i][j]);
                    sc[i][j] = fmaf(aq[i].w, bk[j].w, sc[i][j]);
                }
        }

        // scale + mask + row max
        float mx[4];
#pragma unroll
        for (int i = 0; i < 4; i++) mx[i] = -1e30f;
#pragma unroll
        for (int i = 0; i < 4; i++) {
            const int qrow = ty + 16 * i;
#pragma unroll
            for (int j = 0; j < 4; j++) {
                const int mv = Mg[(size_t)qrow * S_ + kt * 64 + tx + 16 * j];
                const float v = mv ? sc[i][j] * 0.125f : -1.0e9f;
                sc[i][j] = v;
                mx[i] = fmaxf(mx[i], v);
            }
        }
#pragma unroll
        for (int sft = 8; sft >= 1; sft >>= 1)
#pragma unroll
            for (int i = 0; i < 4; i++)
                mx[i] = fmaxf(mx[i], __shfl_xor_sync(0xffffffffu, mx[i], sft));

        float al[4], rs[4];
#pragma unroll
        for (int i = 0; i < 4; i++) {
            const float mn = fmaxf(m_i[i], mx[i]);
            al[i] = __expf(m_i[i] - mn);
            m_i[i] = mn;
            rs[i] = 0.0f;
#pragma unroll
            for (int j = 0; j < 4; j++) {
                const float p = __expf(sc[i][j] - mn);
                sc[i][j] = p;
                rs[i] += p;
            }
        }
#pragma unroll
        for (int sft = 8; sft >= 1; sft >>= 1)
#pragma unroll
            for (int i = 0; i < 4; i++)
                rs[i] += __shfl_xor_sync(0xffffffffu, rs[i], sft);
#pragma unroll
        for (int i = 0; i < 4; i++) {
            l_i[i] = l_i[i] * al[i] + rs[i];
#pragma unroll
            for (int j = 0; j < 4; j++) o[i][j] *= al[i];
        }

        __syncthreads();   // all S-compute reads of Ks done before overwrite
        // store P transposed: P^T[k][q]  (conflict-free stores & reads)
#pragma unroll
        for (int i = 0; i < 4; i++)
#pragma unroll
            for (int j = 0; j < 4; j++)
                Ks[(tx + 16 * j) * AST + ty + 16 * i] = sc[i][j];
        __syncthreads();

        // O += P @ V : thread owns rows ty+16i, V-cols tx*4..tx*4+3
#pragma unroll 4
        for (int k2 = 0; k2 < 64; k2++) {
            float pv[4];
#pragma unroll
            for (int i = 0; i < 4; i++) pv[i] = Ks[k2 * AST + ty + 16 * i];
            const float4 vv = *(const float4*)&Vs[k2 * AST + tx * 4];
#pragma unroll
            for (int i = 0; i < 4; i++) {
                o[i][0] = fmaf(pv[i], vv.x, o[i][0]);
                o[i][1] = fmaf(pv[i], vv.y, o[i][1]);
                o[i][2] = fmaf(pv[i], vv.z, o[i][2]);
                o[i][3] = fmaf(pv[i], vv.w, o[i][3]);
            }
        }
    }

    // normalize and write merged-head output [B,S,D]
#pragma unroll
    for (int i = 0; i < 4; i++) {
        const int s = qb * 64 + ty + 16 * i;
        const float inv = 1.0f / l_i[i];
        const float4 res = make_float4(o[i][0] * inv, o[i][1] * inv,
                                       o[i][2] * inv, o[i][3] * inv);
        *(float4*)&O[((size_t)b * S_ + s) * D_ + h * 64 + tx * 4] = res;
    }
}

// =====================================================================
// launcher
// =====================================================================
extern "C" void kernel_launch(void* const* d_in, const int* in_sizes, int n_in,
                              void* d_out, int out_size)
{
    (void)in_sizes; (void)n_in; (void)out_size;
    const float* q    = (const float*)d_in[0];
    const float* k    = (const float*)d_in[1];
    const float* v    = (const float*)d_in[2];
    const int*   mask = (const int*)  d_in[3];
    const float* Wq   = (const float*)d_in[4];
    const float* bq   = (const float*)d_in[5];
    const float* Wk   = (const float*)d_in[6];
    const float* bk   = (const float*)d_in[7];
    const float* Wv   = (const float*)d_in[8];
    const float* bv   = (const float*)d_in[9];
    const float* Wo   = (const float*)d_in[10];
    const float* bo   = (const float*)d_in[11];
    float* out = (float*)d_out;

    float *qp, *kp, *vp, *at;
    cudaGetSymbolAddress((void**)&qp, g_Qp);
    cudaGetSymbolAddress((void**)&kp, g_Kp);
    cudaGetSymbolAddress((void**)&vp, g_Vp);
    cudaGetSymbolAddress((void**)&at, g_At);

    cudaFuncSetAttribute(attn_kernel, cudaFuncAttributeMaxDynamicSharedMemorySize,
                         3 * 64 * AST * (int)sizeof(float));

    const dim3 ggrid(D_ / 128, (B_ * S_) / 128);   // (8, 64)
    const dim3 gblk(256);

    // QKV projections -> head-split layout
    gemm_nt<true><<<ggrid, gblk>>>(q, Wq, bq, qp);
    gemm_nt<true><<<ggrid, gblk>>>(k, Wk, bk, kp);
    gemm_nt<true><<<ggrid, gblk>>>(v, Wv, bv, vp);

    // flash attention -> merged [B,S,D]
    const dim3 agrid(S_ / 64, B_ * H_);            // (32, 64)
    attn_kernel<<<agrid, 256, 3 * 64 * AST * sizeof(float)>>>(qp, kp, vp, mask, at);

    // output projection -> d_out
    gemm_nt<false><<<ggrid, gblk>>>(at, Wo, bo, out);
}

// round 6
// speedup vs baseline: 4.5250x; 4.5250x over previous
#include <cuda_runtime.h>
#include <cuda_fp16.h>
#include <math.h>

#define B_   4
#define S_   2048
#define D_   1024
#define H_   16
#define DK_  64

// ---------------- fp16 scratch (static device globals: allocation-free) ----------------
__device__ __half g_Qp[(size_t)B_ * H_ * S_ * DK_];   // [B,H,S,dk]
__device__ __half g_Kp[(size_t)B_ * H_ * S_ * DK_];   // [B,H,S,dk]
__device__ __half g_Vt[(size_t)B_ * H_ * DK_ * S_];   // [B,H,dk,S]  (transposed!)
__device__ __half g_At[(size_t)B_ * S_ * D_];         // attention out, merged [B,S,D]

__device__ __forceinline__ unsigned packh2(float x, float y) {
    __half2 h = __floats2half2_rn(x, y);
    return *reinterpret_cast<unsigned*>(&h);
}

// D += A(16x16 f16) @ B(16x8 f16), fp32 accumulate
__device__ __forceinline__ void mma_f16(float* d, const unsigned* a, const unsigned* b) {
    asm volatile(
        "mma.sync.aligned.m16n8k16.row.col.f32.f16.f16.f32 "
        "{%0,%1,%2,%3}, {%4,%5,%6,%7}, {%8,%9}, {%0,%1,%2,%3};\n"
        : "+f"(d[0]), "+f"(d[1]), "+f"(d[2]), "+f"(d[3])
        : "r"(a[0]), "r"(a[1]), "r"(a[2]), "r"(a[3]),
          "r"(b[0]), "r"(b[1]));
}

// =====================================================================
// GEMM core:  acc = A[8192 x 1024] @ W^T   (W row-major [N=1024, K=1024])
// BM=128, BN=128, BK=32, 256 threads = 8 warps (4m x 2n), warp tile 32x64.
// SMEM half tiles, stride 40 (bank = 4g+c : conflict-free fragment loads).
// =====================================================================
#define GS 40

template <bool AHALF>
__device__ __forceinline__ void gemm_body(const void* __restrict__ Aptr,
                                          const float* __restrict__ W,
                                          __half* As, __half* Ws,
                                          float acc[2][8][4])
{
    const int tid  = threadIdx.x;
    const int lane = tid & 31, wid = tid >> 5;
    const int g = lane >> 2, c = lane & 3;
    const int m0 = (wid >> 1) * 32, n0 = (wid & 1) * 64;
    const int bm = blockIdx.y, bn = blockIdx.x;

    int r_[4], c_[4];
#pragma unroll
    for (int i = 0; i < 4; i++) { int idx = tid + 256 * i; r_[i] = idx >> 3; c_[i] = (idx & 7) * 4; }

#pragma unroll
    for (int mt = 0; mt < 2; mt++)
#pragma unroll
        for (int nt = 0; nt < 8; nt++)
#pragma unroll
            for (int i = 0; i < 4; i++) acc[mt][nt][i] = 0.0f;

    const float*  Af = (const float*)Aptr;
    const __half* Ah = (const __half*)Aptr;

    uint2  abuf[4];
    float4 wbuf[4];

    // prefetch k-tile 0
#pragma unroll
    for (int i = 0; i < 4; i++) {
        if (AHALF) {
            abuf[i] = *(const uint2*)&Ah[(size_t)(bm * 128 + r_[i]) * 1024 + c_[i]];
        } else {
            const float4 v = *(const float4*)&Af[(size_t)(bm * 128 + r_[i]) * 1024 + c_[i]];
            abuf[i] = make_uint2(packh2(v.x, v.y), packh2(v.z, v.w));
        }
        wbuf[i] = *(const float4*)&W[(size_t)(bn * 128 + r_[i]) * 1024 + c_[i]];
    }

    for (int kt = 0; kt < 32; kt++) {
        __syncthreads();
#pragma unroll
        for (int i = 0; i < 4; i++) {
            *(uint2*)&As[r_[i] * GS + c_[i]] = abuf[i];
            *(uint2*)&Ws[r_[i] * GS + c_[i]] =
                make_uint2(packh2(wbuf[i].x, wbuf[i].y), packh2(wbuf[i].z, wbuf[i].w));
        }
        __syncthreads();

        if (kt < 31) {
            const int kc = (kt + 1) * 32;
#pragma unroll
            for (int i = 0; i < 4; i++) {
                if (AHALF) {
                    abuf[i] = *(const uint2*)&Ah[(size_t)(bm * 128 + r_[i]) * 1024 + kc + c_[i]];
                } else {
                    const float4 v = *(const float4*)&Af[(size_t)(bm * 128 + r_[i]) * 1024 + kc + c_[i]];
                    abuf[i] = make_uint2(packh2(v.x, v.y), packh2(v.z, v.w));
                }
                wbuf[i] = *(const float4*)&W[(size_t)(bn * 128 + r_[i]) * 1024 + kc + c_[i]];
            }
        }

#pragma unroll
        for (int ks = 0; ks < 2; ks++) {
            const int k0 = ks * 16;
            unsigned a[2][4];
#pragma unroll
            for (int mt = 0; mt < 2; mt++) {
                const __half* p = &As[(m0 + mt * 16 + g) * GS + k0 + 2 * c];
                a[mt][0] = *(const unsigned*)p;
                a[mt][1] = *(const unsigned*)(p + 8 * GS);
                a[mt][2] = *(const unsigned*)(p + 8);
                a[mt][3] = *(const unsigned*)(p + 8 * GS + 8);
            }
#pragma unroll
            for (int nt = 0; nt < 8; nt++) {
                const __half* p = &Ws[(n0 + nt * 8 + g) * GS + k0 + 2 * c];
                unsigned b2[2] = { *(const unsigned*)p, *(const unsigned*)(p + 8) };
#pragma unroll
                for (int mt = 0; mt < 2; mt++) mma_f16(acc[mt][nt], a[mt], b2);
            }
        }
    }
}

// ------------------- fused QKV projection (blockIdx.z selects q/k/v) -------------------
__global__ __launch_bounds__(256, 2)
void gemm_qkv(const float* __restrict__ q, const float* __restrict__ k, const float* __restrict__ v,
              const float* __restrict__ Wq, const float* __restrict__ bq,
              const float* __restrict__ Wk, const float* __restrict__ bk,
              const float* __restrict__ Wv, const float* __restrict__ bv)
{
    __shared__ __half As[128 * GS];
    __shared__ __half Ws[128 * GS];

    const int z = blockIdx.z;
    const float* A    = (z == 0) ? q  : (z == 1) ? k  : v;
    const float* W    = (z == 0) ? Wq : (z == 1) ? Wk : Wv;
    const float* bias = (z == 0) ? bq : (z == 1) ? bk : bv;

    float acc[2][8][4];
    gemm_body<false>(A, W, As, Ws, acc);

    const int tid = threadIdx.x, lane = tid & 31, wid = tid >> 5;
    const int g = lane >> 2, c = lane & 3;
    const int m0 = (wid >> 1) * 32, n0 = (wid & 1) * 64;
    const int bm = blockIdx.y, bn = blockIdx.x;

    __half* C01 = (z == 0) ? g_Qp : g_Kp;

#pragma unroll
    for (int nt = 0; nt < 8; nt++) {
        const int col = bn * 128 + n0 + nt * 8 + 2 * c;
        const float b0 = bias[col], b1 = bias[col + 1];
        const int hh = col >> 6, dd = col & 63;
#pragma unroll
        for (int mt = 0; mt < 2; mt++) {
#pragma unroll
            for (int rr = 0; rr < 2; rr++) {
                const int r  = bm * 128 + m0 + mt * 16 + g + rr * 8;
                const int bb = r >> 11, ss = r & 2047;
                const float v0 = acc[mt][nt][rr * 2 + 0] + b0;
                const float v1 = acc[mt][nt][rr * 2 + 1] + b1;
                if (z <= 1) {
                    *(unsigned*)&C01[(((size_t)(bb * H_ + hh)) * S_ + ss) * DK_ + dd] = packh2(v0, v1);
                } else {
                    g_Vt[(((size_t)(bb * H_ + hh)) * DK_ + dd    ) * S_ + ss] = __float2half_rn(v0);
                    g_Vt[(((size_t)(bb * H_ + hh)) * DK_ + dd + 1) * S_ + ss] = __float2half_rn(v1);
                }
            }
        }
    }
}

// ------------------- output projection: out = At @ Wo^T + bo (fp32 out) -------------------
__global__ __launch_bounds__(256, 2)
void gemm_out(const float* __restrict__ Wo, const float* __restrict__ bo,
              float* __restrict__ out)
{
    __shared__ __half As[128 * GS];
    __shared__ __half Ws[128 * GS];

    float acc[2][8][4];
    gemm_body<true>(g_At, Wo, As, Ws, acc);

    const int tid = threadIdx.x, lane = tid & 31, wid = tid >> 5;
    const int g = lane >> 2, c = lane & 3;
    const int m0 = (wid >> 1) * 32, n0 = (wid & 1) * 64;
    const int bm = blockIdx.y, bn = blockIdx.x;

#pragma unroll
    for (int nt = 0; nt < 8; nt++) {
        const int col = bn * 128 + n0 + nt * 8 + 2 * c;
        const float b0 = bo[col], b1 = bo[col + 1];
#pragma unroll
        for (int mt = 0; mt < 2; mt++) {
#pragma unroll
            for (int rr = 0; rr < 2; rr++) {
                const int r = bm * 128 + m0 + mt * 16 + g + rr * 8;
                *(float2*)&out[(size_t)r * 1024 + col] =
                    make_float2(acc[mt][nt][rr * 2 + 0] + b0, acc[mt][nt][rr * 2 + 1] + b1);
            }
        }
    }
}

// =====================================================================
// Flash attention, fp16 mma, fp32 accum + fp32 softmax.
// Block = (bh, 128-query tile), 8 warps; warp w owns q rows 16w..16w+15.
// Key tiles of 64; dk = 64. All SMEM tiles stride 72 halves (bank=4g+c).
// P is per-warp-private -> only __syncwarp between softmax and PV.
// =====================================================================
#define QT 128
#define AS 72

__global__ __launch_bounds__(256, 2)
void attn16(const int* __restrict__ mask)
{
    extern __shared__ __half sh[];
    __half* Qs = sh;                  // 128 * 72
    __half* Ks = Qs + QT * AS;        //  64 * 72
    __half* Vs = Ks + 64 * AS;        //  64 * 72  (holds V^T tile: [dk][key])
    __half* Ps = Vs + 64 * AS;        // 128 * 72

    const int tid = threadIdx.x, lane = tid & 31, w = tid >> 5;
    const int g = lane >> 2, c = lane & 3;
    const int qt = blockIdx.x, bh = blockIdx.y;
    const int b  = bh >> 4,   h  = bh & 15;

    const __half* Qg = g_Qp + ((size_t)bh * S_ + qt * QT) * DK_;
    const __half* Kg = g_Kp + (size_t)bh * S_ * DK_;
    const __half* Vg = g_Vt + (size_t)bh * DK_ * S_;

    // load Q tile 128x64 halves (1024 uint4)
    for (int i = tid; i < 1024; i += 256) {
        const int r = i >> 3, c8 = (i & 7) * 8;
        *(uint4*)&Qs[r * AS + c8] = *(const uint4*)&Qg[r * DK_ + c8];
    }

    const int qr = 16 * w + g;        // warp-local base q row (block-local)

    float rowm[2] = { -1e30f, -1e30f };
    float rowl[2] = { 0.0f, 0.0f };
    float o[8][4];
#pragma unroll
    for (int nt = 0; nt < 8; nt++)
#pragma unroll
        for (int i = 0; i < 4; i++) o[nt][i] = 0.0f;

    for (int kt = 0; kt < S_ / 64; kt++) {
        __syncthreads();
        // load K tile [key][dk] and V^T tile [dk][key], 512 uint4 each
        for (int i = tid; i < 512; i += 256) {
            const int r = i >> 3, c8 = (i & 7) * 8;
            *(uint4*)&Ks[r * AS + c8] = *(const uint4*)&Kg[(size_t)(kt * 64 + r) * DK_ + c8];
            *(uint4*)&Vs[r * AS + c8] = *(const uint4*)&Vg[(size_t)r * S_ + kt * 64 + c8];
        }
        __syncthreads();

        // ---- S = Q @ K^T ----
        float s[8][4];
#pragma unroll
        for (int nt = 0; nt < 8; nt++)
#pragma unroll
            for (int i = 0; i < 4; i++) s[nt][i] = 0.0f;

#pragma unroll
        for (int ks = 0; ks < 4; ks++) {
            const int k0 = ks * 16;
            unsigned a[4];
            const __half* pa = &Qs[qr * AS + k0 + 2 * c];
            a[0] = *(const unsigned*)pa;
            a[1] = *(const unsigned*)(pa + 8 * AS);
            a[2] = *(const unsigned*)(pa + 8);
            a[3] = *(const unsigned*)(pa + 8 * AS + 8);
#pragma unroll
            for (int nt = 0; nt < 8; nt++) {
                const __half* pb = &Ks[(nt * 8 + g) * AS + k0 + 2 * c];
                unsigned b2[2] = { *(const unsigned*)pb, *(const unsigned*)(pb + 8) };
                mma_f16(s[nt], a, b2);
            }
        }

        // ---- scale + mask + online softmax ----
        const size_t mrow0 = (size_t)(qt * QT + qr) * S_ + kt * 64;
        const size_t mrow1 = mrow0 + 8 * S_;
        float mx0 = -1e30f, mx1 = -1e30f;
#pragma unroll
        for (int nt = 0; nt < 8; nt++) {
            const int cc = nt * 8 + 2 * c;
            const int2 m0v = *(const int2*)&mask[mrow0 + cc];
            const int2 m1v = *(const int2*)&mask[mrow1 + cc];
            s[nt][0] = m0v.x ? s[nt][0] * 0.125f : -1.0e9f;
            s[nt][1] = m0v.y ? s[nt][1] * 0.125f : -1.0e9f;
            s[nt][2] = m1v.x ? s[nt][2] * 0.125f : -1.0e9f;
            s[nt][3] = m1v.y ? s[nt][3] * 0.125f : -1.0e9f;
            mx0 = fmaxf(mx0, fmaxf(s[nt][0], s[nt][1]));
            mx1 = fmaxf(mx1, fmaxf(s[nt][2], s[nt][3]));
        }
        mx0 = fmaxf(mx0, __shfl_xor_sync(0xffffffffu, mx0, 1));
        mx0 = fmaxf(mx0, __shfl_xor_sync(0xffffffffu, mx0, 2));
        mx1 = fmaxf(mx1, __shfl_xor_sync(0xffffffffu, mx1, 1));
        mx1 = fmaxf(mx1, __shfl_xor_sync(0xffffffffu, mx1, 2));

        const float mn0 = fmaxf(rowm[0], mx0);
        const float mn1 = fmaxf(rowm[1], mx1);
        const float al0 = __expf(rowm[0] - mn0);
        const float al1 = __expf(rowm[1] - mn1);
        rowm[0] = mn0; rowm[1] = mn1;

        float rs0 = 0.0f, rs1 = 0.0f;
#pragma unroll
        for (int nt = 0; nt < 8; nt++) {
            const float p0 = __expf(s[nt][0] - mn0);
            const float p1 = __expf(s[nt][1] - mn0);
            const float p2 = __expf(s[nt][2] - mn1);
            const float p3 = __expf(s[nt][3] - mn1);
            rs0 += p0 + p1;
            rs1 += p2 + p3;
            *(unsigned*)&Ps[ qr      * AS + nt * 8 + 2 * c] = packh2(p0, p1);
            *(unsigned*)&Ps[(qr + 8) * AS + nt * 8 + 2 * c] = packh2(p2, p3);
        }
        rs0 += __shfl_xor_sync(0xffffffffu, rs0, 1);
        rs0 += __shfl_xor_sync(0xffffffffu, rs0, 2);
        rs1 += __shfl_xor_sync(0xffffffffu, rs1, 1);
        rs1 += __shfl_xor_sync(0xffffffffu, rs1, 2);
        rowl[0] = rowl[0] * al0 + rs0;
        rowl[1] = rowl[1] * al1 + rs1;
#pragma unroll
        for (int nt = 0; nt < 8; nt++) {
            o[nt][0] *= al0; o[nt][1] *= al0;
            o[nt][2] *= al1; o[nt][3] *= al1;
        }

        __syncwarp();   // P rows are warp-private; order STS -> mma A-frag loads

        // ---- O += P @ V  (k = key, n = dk; Vs is [dk][key]) ----
#pragma unroll
        for (int ks = 0; ks < 4; ks++) {
            const int k0 = ks * 16;
            unsigned a[4];
            const __half* pa = &Ps[qr * AS + k0 + 2 * c];
            a[0] = *(const unsigned*)pa;
            a[1] = *(const unsigned*)(pa + 8 * AS);
            a[2] = *(const unsigned*)(pa + 8);
            a[3] = *(const unsigned*)(pa + 8 * AS + 8);
#pragma unroll
            for (int nt = 0; nt < 8; nt++) {
                const __half* pb = &Vs[(nt * 8 + g) * AS + k0 + 2 * c];
                unsigned b2[2] = { *(const unsigned*)pb, *(const unsigned*)(pb + 8) };
                mma_f16(o[nt], a, b2);
            }
        }
    }

    // ---- normalize, write merged-head fp16 output [B,S,D] ----
    const float inv0 = 1.0f / rowl[0];
    const float inv1 = 1.0f / rowl[1];
    const int s0 = qt * QT + qr;
#pragma unroll
    for (int nt = 0; nt < 8; nt++) {
        const int col = h * 64 + nt * 8 + 2 * c;
        *(unsigned*)&g_At[(size_t)(b * S_ + s0    ) * D_ + col] = packh2(o[nt][0] * inv0, o[nt][1] * inv0);
        *(unsigned*)&g_At[(size_t)(b * S_ + s0 + 8) * D_ + col] = packh2(o[nt][2] * inv1, o[nt][3] * inv1);
    }
}

// =====================================================================
// launcher
// =====================================================================
extern "C" void kernel_launch(void* const* d_in, const int* in_sizes, int n_in,
                              void* d_out, int out_size)
{
    (void)in_sizes; (void)n_in; (void)out_size;
    const float* q    = (const float*)d_in[0];
    const float* k    = (const float*)d_in[1];
    const float* v    = (const float*)d_in[2];
    const int*   mask = (const int*)  d_in[3];
    const float* Wq   = (const float*)d_in[4];
    const float* bq   = (const float*)d_in[5];
    const float* Wk   = (const float*)d_in[6];
    const float* bk   = (const float*)d_in[7];
    const float* Wv   = (const float*)d_in[8];
    const float* bv   = (const float*)d_in[9];
    const float* Wo   = (const float*)d_in[10];
    const float* bo   = (const float*)d_in[11];
    float* out = (float*)d_out;

    const int attn_smem = (QT * AS + 64 * AS + 64 * AS + QT * AS) * (int)sizeof(__half);
    cudaFuncSetAttribute(attn16, cudaFuncAttributeMaxDynamicSharedMemorySize, attn_smem);

    // fused QKV projections (z = 0:Q, 1:K, 2:V-transposed)
    gemm_qkv<<<dim3(D_ / 128, (B_ * S_) / 128, 3), 256>>>(q, k, v, Wq, bq, Wk, bk, Wv, bv);

    // flash attention -> merged fp16 [B,S,D]
    attn16<<<dim3(S_ / QT, B_ * H_), 256, attn_smem>>>(mask);

    // output projection -> fp32 d_out
    gemm_out<<<dim3(D_ / 128, (B_ * S_) / 128), 256>>>(Wo, bo, out);
}